// round 11
// baseline (speedup 1.0000x reference)
#include <cuda_runtime.h>
#include <stdint.h>
#include <float.h>

// Shapes: data [64,1024,256] f32, locs [64,256,2] f32, out [64,1024,2500] f32
#define B_   64
#define T_   1024
#define N_   256
#define G_   50
#define GG   2500
#define TPB  256
#define R_   8                       // t-rows per gather item (window)
#define SLICES 320                   // 64 batches x 5 slices of 512 cells
#define CELLS_PER_SLICE 512
#define WINDOWS_PER_BATCH (T_ / R_)  // 128
#define ITEMS (B_ * WINDOWS_PER_BATCH)   // 8192
#define SPIN_LIMIT 200000

__device__ uint8_t  g_nearest[B_ * GG];
__device__ unsigned g_arrive;        // device-barrier arrivals
__device__ unsigned g_finish;        // completion counter (replay reset)

union SmemU {
    struct { float4 sen[N_]; } p;                                   // producer
    struct { float4 rowsA[N_], rowsB[N_]; uint8_t sidx[GG]; } g;    // gather
};

// ---------------------------------------------------------------------------
// Producer slice s: cells [(s%5)*512, +512) of batch s/5, 2 cells/thread.
// Exact jnp.argmin(sqrt(dx^2+dy^2)) reproduction (rel_err=0 since R4):
//  Pass 1: branchless min of e_j = c_j - 2sx*gx - 2sy*gy (|e err| <= ~3e-3;
//          sqrt-tie class width <= ~1.5e-3 => thresh = emin+0.02 is safe).
//  Pass 2: exact rn-rounded d2 (no FMA contraction) + __fsqrt_rn for rare
//          candidates; strict < ascending j => first-index-wins.
// Deterministic => byte-idempotent (redundant production harmless).
// ---------------------------------------------------------------------------
__device__ __forceinline__ void produce_slice(SmemU& sm, int s,
                                              const float* __restrict__ locs,
                                              int tid) {
    const int b     = s / 5;
    const int cbase = (s % 5) * CELLS_PER_SLICE;

    __syncthreads();                 // protect sen[] reuse
    {
        float2 l = reinterpret_cast<const float2*>(locs)[b * N_ + tid];
        float sx = __fadd_rn(__fmul_rn(l.x, 25.0f), 25.0f);   // exact ref transform
        float sy = __fadd_rn(__fmul_rn(l.y, 25.0f), 25.0f);
        sm.p.sen[tid] = make_float4(sx, sy, sx * sx + sy * sy, 0.0f);
    }
    __syncthreads();

    const int g0 = cbase + tid;
    const int g1 = g0 + TPB;
    const float gxa = (float)(g0 / G_), gya = (float)(g0 % G_);
    const float gxb = (float)(g1 / G_), gyb = (float)(g1 % G_);
    const float axa = -2.0f * gxa, aya = -2.0f * gya;         // exact small ints
    const float axb = -2.0f * gxb, ayb = -2.0f * gyb;

    float ma0 = FLT_MAX, ma1 = FLT_MAX, mb0 = FLT_MAX, mb1 = FLT_MAX;
    #pragma unroll 8
    for (int j = 0; j < N_; j += 2) {
        float4 s0 = sm.p.sen[j];
        float4 s1 = sm.p.sen[j + 1];
        ma0 = fminf(ma0, __fmaf_rn(s0.y, aya, __fmaf_rn(s0.x, axa, s0.z)));
        mb0 = fminf(mb0, __fmaf_rn(s0.y, ayb, __fmaf_rn(s0.x, axb, s0.z)));
        ma1 = fminf(ma1, __fmaf_rn(s1.y, aya, __fmaf_rn(s1.x, axa, s1.z)));
        mb1 = fminf(mb1, __fmaf_rn(s1.y, ayb, __fmaf_rn(s1.x, axb, s1.z)));
    }
    const float ta = fminf(ma0, ma1) + 0.02f;
    const float tb = fminf(mb0, mb1) + 0.02f;

    float bsa = FLT_MAX, bsb = FLT_MAX;
    int   bia = 0,       bib = 0;
    #pragma unroll 4
    for (int j = 0; j < N_; ++j) {
        float4 sv = sm.p.sen[j];
        float ea = __fmaf_rn(sv.y, aya, __fmaf_rn(sv.x, axa, sv.z));
        float eb = __fmaf_rn(sv.y, ayb, __fmaf_rn(sv.x, axb, sv.z));
        if (ea <= ta) {                                       // ~1 hit per cell
            float dx = __fsub_rn(sv.x, gxa);
            float dy = __fsub_rn(sv.y, gya);
            float d2 = __fadd_rn(__fmul_rn(dx, dx), __fmul_rn(dy, dy));
            float sq = __fsqrt_rn(d2);
            if (sq < bsa) { bsa = sq; bia = j; }
        }
        if (eb <= tb) {
            float dx = __fsub_rn(sv.x, gxb);
            float dy = __fsub_rn(sv.y, gyb);
            float d2 = __fadd_rn(__fmul_rn(dx, dx), __fmul_rn(dy, dy));
            float sq = __fsqrt_rn(d2);
            if (sq < bsb) { bsb = sq; bib = j; }
        }
    }
    if (g0 < GG) g_nearest[b * GG + g0] = (uint8_t)bia;
    if (g1 < GG) g_nearest[b * GG + g1] = (uint8_t)bib;
}

// ---------------------------------------------------------------------------
// Persistent kernel, grid = 3 x numSMs (co-resident by __launch_bounds__).
// Phase 1: grid-stride slice production. Device barrier (bounded spin +
// idempotent fallback => terminates under any schedule). Phase 2: STATIC
// batch-contiguous item partition — each block owns ~19 consecutive windows
// (<=2 batch switches => sidx staged 1-2x per block, store bursts stay tight).
// ---------------------------------------------------------------------------
__global__ __launch_bounds__(TPB, 3)
void persistent_kernel(const float* __restrict__ data,
                       const float* __restrict__ locs,
                       float* __restrict__ out) {
    __shared__ SmemU sm;
    __shared__ int s_timeout;

    const int tid = threadIdx.x;

    // ---- phase 1: produce nearest-index slices ----------------------------
    for (int s = blockIdx.x; s < SLICES; s += gridDim.x)
        produce_slice(sm, s, locs, tid);

    // ---- device barrier ----------------------------------------------------
    __threadfence();                           // release g_nearest writes
    __syncthreads();
    if (tid == 0) {
        s_timeout = 0;
        atomicAdd(&g_arrive, 1u);
        int spins = 0;
        while (atomicAdd(&g_arrive, 0u) < gridDim.x) {
            __nanosleep(64);
            if (++spins > SPIN_LIMIT) { s_timeout = 1; break; }
        }
    }
    __syncthreads();
    if (s_timeout) {                           // unreachable when co-resident
        for (int s = 0; s < SLICES; ++s)       // idempotent full production
            produce_slice(sm, s, locs, tid);
        __syncthreads();
    }
    __threadfence();                           // acquire all slices

    // ---- phase 2: static contiguous gather partition -----------------------
    const int chunk = (ITEMS + gridDim.x - 1) / gridDim.x;   // ~19
    const int start = blockIdx.x * chunk;
    const int end   = min(start + chunk, ITEMS);

    int curb = -1;
    int idx[3][4];

    for (int item = start; item < end; ++item) {
        const int b  = item / WINDOWS_PER_BATCH;
        const int t0 = (item % WINDOWS_PER_BATCH) * R_;

        if (b != curb) {                       // 1-2x per block
            curb = b;
            __syncthreads();                   // done with prior sidx/rows
            const uint32_t* src =
                reinterpret_cast<const uint32_t*>(g_nearest + (size_t)b * GG);
            uint32_t* dst = reinterpret_cast<uint32_t*>(sm.g.sidx);
            #pragma unroll
            for (int k = tid; k < GG / 4; k += TPB) dst[k] = __ldcg(src + k);
            __syncthreads();
            #pragma unroll
            for (int gi = 0; gi < 3; ++gi) {
                int k = tid + gi * TPB;
                if (k < GG / 4) {
                    idx[gi][0] = sm.g.sidx[4 * k + 0];
                    idx[gi][1] = sm.g.sidx[4 * k + 1];
                    idx[gi][2] = sm.g.sidx[4 * k + 2];
                    idx[gi][3] = sm.g.sidx[4 * k + 3];
                }
            }
        }

        __syncthreads();                       // rowsA/B reuse
        {   // stage 8 t-rows transposed (thread tid owns sensor tid)
            const float* d0 = data + ((size_t)b * T_ + t0) * (size_t)N_ + tid;
            float4 va, vb;
            va.x = __ldcs(d0 + 0 * N_);
            va.y = __ldcs(d0 + 1 * N_);
            va.z = __ldcs(d0 + 2 * N_);
            va.w = __ldcs(d0 + 3 * N_);
            vb.x = __ldcs(d0 + 4 * N_);
            vb.y = __ldcs(d0 + 5 * N_);
            vb.z = __ldcs(d0 + 6 * N_);
            vb.w = __ldcs(d0 + 7 * N_);
            sm.g.rowsA[tid] = va;
            sm.g.rowsB[tid] = vb;
        }
        __syncthreads();

        float* o = out + ((size_t)b * T_ + t0) * (size_t)GG;
        #pragma unroll
        for (int gi = 0; gi < 3; ++gi) {
            int k = tid + gi * TPB;
            if (k < GG / 4) {
                float4 a0 = sm.g.rowsA[idx[gi][0]];
                float4 a1 = sm.g.rowsA[idx[gi][1]];
                float4 a2 = sm.g.rowsA[idx[gi][2]];
                float4 a3 = sm.g.rowsA[idx[gi][3]];
                __stcs(reinterpret_cast<float4*>(o + 0 * GG) + k,
                       make_float4(a0.x, a1.x, a2.x, a3.x));
                __stcs(reinterpret_cast<float4*>(o + 1 * GG) + k,
                       make_float4(a0.y, a1.y, a2.y, a3.y));
                __stcs(reinterpret_cast<float4*>(o + 2 * GG) + k,
                       make_float4(a0.z, a1.z, a2.z, a3.z));
                __stcs(reinterpret_cast<float4*>(o + 3 * GG) + k,
                       make_float4(a0.w, a1.w, a2.w, a3.w));
                float4 b0 = sm.g.rowsB[idx[gi][0]];
                float4 b1 = sm.g.rowsB[idx[gi][1]];
                float4 b2 = sm.g.rowsB[idx[gi][2]];
                float4 b3 = sm.g.rowsB[idx[gi][3]];
                __stcs(reinterpret_cast<float4*>(o + 4 * GG) + k,
                       make_float4(b0.x, b1.x, b2.x, b3.x));
                __stcs(reinterpret_cast<float4*>(o + 5 * GG) + k,
                       make_float4(b0.y, b1.y, b2.y, b3.y));
                __stcs(reinterpret_cast<float4*>(o + 6 * GG) + k,
                       make_float4(b0.z, b1.z, b2.z, b3.z));
                __stcs(reinterpret_cast<float4*>(o + 7 * GG) + k,
                       make_float4(b0.w, b1.w, b2.w, b3.w));
            }
        }
    }

    // ---- replay-safe reset: last block clears counters ---------------------
    __syncthreads();
    if (tid == 0) {
        unsigned f = atomicAdd(&g_finish, 1u);
        if (f == gridDim.x - 1u) {
            g_arrive = 0u;
            g_finish = 0u;
            __threadfence();
        }
    }
}

// ---------------------------------------------------------------------------
extern "C" void kernel_launch(void* const* d_in, const int* in_sizes, int n_in,
                              void* d_out, int out_size) {
    const float* data = (const float*)d_in[0];
    const float* locs = (const float*)d_in[1];
    if (n_in >= 2 && in_sizes[0] < in_sizes[1]) {
        data = (const float*)d_in[1];
        locs = (const float*)d_in[0];
    }
    float* out = (float*)d_out;

    int sms = 148;
    cudaDeviceGetAttribute(&sms, cudaDevAttrMultiProcessorCount, 0);
    const int grid = sms * 3;                  // guaranteed-resident set

    persistent_kernel<<<grid, TPB>>>(data, locs, out);
}